// round 9
// baseline (speedup 1.0000x reference)
#include <cuda_runtime.h>
#include <cstdint>

// FP16 pulse (16 floats 0.0/1.0) -> FP8 E4M3 pulse (8 floats). HBM-bound stream.
// R1 226.9us / R6 226.0us both saturate DRAM at ~90% (7.16 TB/s) with totally
// different shapes -> DRAM-efficiency wall. R9: R6 coalesced+ballot pattern, but
// TWO warp-tiles per warp, straight-line (no loop), both tiles' 32 LDG.32
// front-batched so tile-A compute overlaps tile-B load latency. Halves CTA
// count (32768) and wave/tail events; per-SM outstanding loads unchanged.

__device__ __forceinline__ unsigned convert_em(unsigned h) {
    // h bit b = pulse bit b ([S,E4..E0,M9..M0] MSB-first)
    unsigned rev = __brev(h);
    unsigned s = rev >> 31;
    unsigned e = (rev >> 26) & 31u;
    unsigned m = (rev >> 16) & 0x3FFu;

    // normal path (fp16 exp 9..22): RNE(m >> 7), carry bumps exponent
    unsigned keep = m >> 7;
    unsigned sticky_n = (m & 63u) ? 1u : 0u;
    unsigned up_n = ((m >> 6) & 1u) & (sticky_n | (keep & 1u));
    unsigned mr = keep + up_n;                               // 0..8
    unsigned norm = (((e - 8u) + (mr >> 3)) << 3) | (mr & 7u);

    // subnormal path (fp16 exp 5..8): msub = RNE((1024+m) >> (16-e));
    // msub==8 promotes to E=1,M=0 == packed 8, so msub IS the packed E<<3|M
    unsigned xx = 1024u + m;
    int kk_i = 16 - (int)e;
    unsigned kk = (unsigned)min(max(kk_i, 8), 11);
    unsigned keep2 = xx >> kk;
    unsigned low = (1u << (kk - 1u)) - 1u;
    unsigned sticky_s = (xx & low) ? 1u : 0u;
    unsigned up_s = ((xx >> (kk - 1u)) & 1u) & (sticky_s | (keep2 & 1u));
    unsigned msub = keep2 + up_s;

    unsigned em = (e > 22u) ? 0x7Eu
                : (e < 5u)  ? 0u
                : (e <= 8u) ? msub
                :             norm;
    return (s << 7) | em;            // packed S|E4|M3
}

// Mux tree: lane picks its 16-bit descriptor out of the 16 ballot words.
__device__ __forceinline__ unsigned pick_h(const unsigned* B, int lane) {
    unsigned idx = (unsigned)(lane >> 1);
    unsigned u0 = (idx & 1) ? B[1]  : B[0];
    unsigned u1 = (idx & 1) ? B[3]  : B[2];
    unsigned u2 = (idx & 1) ? B[5]  : B[4];
    unsigned u3 = (idx & 1) ? B[7]  : B[6];
    unsigned u4 = (idx & 1) ? B[9]  : B[8];
    unsigned u5 = (idx & 1) ? B[11] : B[10];
    unsigned u6 = (idx & 1) ? B[13] : B[12];
    unsigned u7 = (idx & 1) ? B[15] : B[14];
    unsigned v0 = (idx & 2) ? u1 : u0;
    unsigned v1 = (idx & 2) ? u3 : u2;
    unsigned v2 = (idx & 2) ? u5 : u4;
    unsigned v3 = (idx & 2) ? u7 : u6;
    unsigned x0 = (idx & 4) ? v1 : v0;
    unsigned x1 = (idx & 4) ? v3 : v2;
    unsigned Bw = (idx & 8) ? x1 : x0;
    return (Bw >> ((lane & 1) * 16)) & 0xFFFFu;
}

// Shuffle-align packed results and emit two lane-contiguous STG.128.
__device__ __forceinline__ void store_tile(uint4* q, unsigned R, int lane) {
    unsigned Ra = __shfl_sync(0xffffffffu, R, lane >> 1);
    unsigned Rb = __shfl_sync(0xffffffffu, R, 16 + (lane >> 1));
    int bsh = 7 - 4 * (lane & 1);    // half 0: bits 7..4 ; half 1: bits 3..0
    const unsigned ONE = 0x3F800000u;
    uint4 oA, oB;
    oA.x = ((Ra >> bsh)       & 1u) * ONE;
    oA.y = ((Ra >> (bsh - 1)) & 1u) * ONE;
    oA.z = ((Ra >> (bsh - 2)) & 1u) * ONE;
    oA.w = ((Ra >> (bsh - 3)) & 1u) * ONE;
    oB.x = ((Rb >> bsh)       & 1u) * ONE;
    oB.y = ((Rb >> (bsh - 1)) & 1u) * ONE;
    oB.z = ((Rb >> (bsh - 2)) & 1u) * ONE;
    oB.w = ((Rb >> (bsh - 3)) & 1u) * ONE;
    q[lane]      = oA;
    q[32 + lane] = oB;
}

__global__ void __launch_bounds__(256, 4)
fp16_to_fp8_kernel(const float* __restrict__ in, uint4* __restrict__ out, int npair) {
    int gt   = blockIdx.x * 256 + threadIdx.x;
    int W    = gt >> 5;          // warp-pair id: owns tiles 2W and 2W+1 (64 elements)
    int lane = gt & 31;
    if (W >= npair) return;      // uniform per warp

    // ---- front-batch BOTH tiles' coalesced loads (32 outstanding LDG.32/thread)
    const float* p = in + (size_t)W * 1024 + lane;
    float fa[16], fb[16];
#pragma unroll
    for (int k = 0; k < 16; k++) fa[k] = p[32 * k];
#pragma unroll
    for (int k = 0; k < 16; k++) fb[k] = p[512 + 32 * k];

    // ---- tile A: ballot transpose -> convert -> store (overlaps tile B loads)
    unsigned BA[16];
#pragma unroll
    for (int k = 0; k < 16; k++) BA[k] = __ballot_sync(0xffffffffu, fa[k] != 0.0f);
    unsigned hA = pick_h(BA, lane);
    unsigned RA = convert_em(hA);
    store_tile(out + (size_t)W * 128, RA, lane);

    // ---- tile B
    unsigned BB[16];
#pragma unroll
    for (int k = 0; k < 16; k++) BB[k] = __ballot_sync(0xffffffffu, fb[k] != 0.0f);
    unsigned hB = pick_h(BB, lane);
    unsigned RB = convert_em(hB);
    store_tile(out + (size_t)W * 128 + 64, RB, lane);
}

extern "C" void kernel_launch(void* const* d_in, const int* in_sizes, int n_in,
                              void* d_out, int out_size) {
    const float* in = (const float*)d_in[0];
    uint4* out = (uint4*)d_out;
    int n = in_sizes[0] / 16;            // elements (4096*4096)
    int npair = n / 64;                  // 64 elements per warp; n divisible by 64
    int threads = 256;
    int blocks = (npair * 32 + threads - 1) / threads;   // 32768
    fp16_to_fp8_kernel<<<blocks, threads>>>(in, out, npair);
}

// round 10
// speedup vs baseline: 1.0031x; 1.0031x over previous
#include <cuda_runtime.h>
#include <cstdint>

// FP16 pulse (16 floats 0.0/1.0) -> FP8 E4M3 pulse (8 floats). HBM-bound stream.
// R1/R6/R9 all saturate at ~7.15 TB/s (90% DRAM) regardless of shape -> mixed
// R/W DRAM ceiling. R10: R6 champion + __stcs on STORES only (single variable):
// evict-first dirty lines may smooth writeback bursts against the read stream.
// Loads stay default-cached.

__global__ void __launch_bounds__(256)
fp16_to_fp8_kernel(const float* __restrict__ in, uint4* __restrict__ out, int nwarp) {
    int gt   = blockIdx.x * 256 + threadIdx.x;
    int w    = gt >> 5;          // global warp id: owns elements [32w, 32w+32)
    int lane = gt & 31;
    if (w >= nwarp) return;      // uniform per warp

    // ---- coalesced loads: lane L takes float word 512w + 32k + L (1 wf/instr)
    const float* p = in + (size_t)w * 512 + lane;
    float f[16];
#pragma unroll
    for (int k = 0; k < 16; k++) f[k] = p[32 * k];

    // ---- ballot transpose: B[k] bit L = pulse bit (L&15) of element 32w+2k+(L>=16)
    unsigned B[16];
#pragma unroll
    for (int k = 0; k < 16; k++) B[k] = __ballot_sync(0xffffffffu, f[k] != 0.0f);

    // ---- lane L's element is 32w+L: halfword from B[L>>1], half (L&1)
    unsigned idx = (unsigned)(lane >> 1);
    unsigned u0 = (idx & 1) ? B[1]  : B[0];
    unsigned u1 = (idx & 1) ? B[3]  : B[2];
    unsigned u2 = (idx & 1) ? B[5]  : B[4];
    unsigned u3 = (idx & 1) ? B[7]  : B[6];
    unsigned u4 = (idx & 1) ? B[9]  : B[8];
    unsigned u5 = (idx & 1) ? B[11] : B[10];
    unsigned u6 = (idx & 1) ? B[13] : B[12];
    unsigned u7 = (idx & 1) ? B[15] : B[14];
    unsigned v0 = (idx & 2) ? u1 : u0;
    unsigned v1 = (idx & 2) ? u3 : u2;
    unsigned v2 = (idx & 2) ? u5 : u4;
    unsigned v3 = (idx & 2) ? u7 : u6;
    unsigned x0 = (idx & 4) ? v1 : v0;
    unsigned x1 = (idx & 4) ? v3 : v2;
    unsigned Bw = (idx & 8) ? x1 : x0;
    unsigned h  = (Bw >> ((lane & 1) * 16)) & 0xFFFFu;

    // ---- unpack: h bit b = pulse bit b ([S,E4..E0,M9..M0] MSB-first)
    unsigned rev = __brev(h);
    unsigned s = rev >> 31;
    unsigned e = (rev >> 26) & 31u;
    unsigned m = (rev >> 16) & 0x3FFu;

    // ---- normal path (fp16 exp 9..22): RNE(m >> 7), carry bumps exponent
    unsigned keep = m >> 7;
    unsigned sticky_n = (m & 63u) ? 1u : 0u;
    unsigned up_n = ((m >> 6) & 1u) & (sticky_n | (keep & 1u));
    unsigned mr = keep + up_n;                               // 0..8
    unsigned norm = (((e - 8u) + (mr >> 3)) << 3) | (mr & 7u);

    // ---- subnormal path (fp16 exp 5..8): msub = RNE((1024+m) >> (16-e));
    // msub==8 promotes to E=1,M=0 == packed 8, so msub IS the packed E<<3|M
    unsigned xx = 1024u + m;
    int kk_i = 16 - (int)e;
    unsigned kk = (unsigned)min(max(kk_i, 8), 11);
    unsigned keep2 = xx >> kk;
    unsigned low = (1u << (kk - 1u)) - 1u;
    unsigned sticky_s = (xx & low) ? 1u : 0u;
    unsigned up_s = ((xx >> (kk - 1u)) & 1u) & (sticky_s | (keep2 & 1u));
    unsigned msub = keep2 + up_s;

    unsigned em = (e > 22u) ? 0x7Eu
                : (e < 5u)  ? 0u
                : (e <= 8u) ? msub
                :             norm;
    unsigned R = (s << 7) | em;      // packed S|E4|M3 for element 32w+lane

    // ---- coalesced stores (evict-first): out uint4 index 64w+q
    // lane L stores q=L (needs R of elem L>>1) and q=32+L (elem 16+(L>>1))
    unsigned Ra = __shfl_sync(0xffffffffu, R, lane >> 1);
    unsigned Rb = __shfl_sync(0xffffffffu, R, 16 + (lane >> 1));
    int bsh = 7 - 4 * (lane & 1);    // half 0: bits 7..4 ; half 1: bits 3..0
    const unsigned ONE = 0x3F800000u;
    uint4 oA, oB;
    oA.x = ((Ra >> bsh)       & 1u) * ONE;
    oA.y = ((Ra >> (bsh - 1)) & 1u) * ONE;
    oA.z = ((Ra >> (bsh - 2)) & 1u) * ONE;
    oA.w = ((Ra >> (bsh - 3)) & 1u) * ONE;
    oB.x = ((Rb >> bsh)       & 1u) * ONE;
    oB.y = ((Rb >> (bsh - 1)) & 1u) * ONE;
    oB.z = ((Rb >> (bsh - 2)) & 1u) * ONE;
    oB.w = ((Rb >> (bsh - 3)) & 1u) * ONE;

    uint4* q = out + (size_t)w * 64;
    __stcs(q + lane,      oA);
    __stcs(q + 32 + lane, oB);
}

extern "C" void kernel_launch(void* const* d_in, const int* in_sizes, int n_in,
                              void* d_out, int out_size) {
    const float* in = (const float*)d_in[0];
    uint4* out = (uint4*)d_out;
    int n = in_sizes[0] / 16;            // elements (4096*4096)
    int nwarp = n / 32;                  // 32 elements per warp; n divisible by 32
    int threads = 256;
    int blocks = (nwarp * 32 + threads - 1) / threads;   // 65536
    fp16_to_fp8_kernel<<<blocks, threads>>>(in, out, nwarp);
}